// round 3
// baseline (speedup 1.0000x reference)
#include <cuda_runtime.h>

#define N_NODES 100000
#define E_REAL  3200000
#define E_TOT   3300000
#define IN_CH   256
#define HID     64
#define HEADS1  8
#define OUT_CH  3
#define CNT_PAD 100352   // 196 * 512

// ---------------- scratch (static device globals; no runtime alloc) ----------------
__device__ int   d_is64;                  // 1 if edge_index is int64, 0 if int32
__device__ int   d_cnt[CNT_PAD];          // degree counts -> scatter cursors
__device__ int   d_rowptr[N_NODES + 1];
__device__ int   d_part[256];             // scan partials
__device__ int   d_col[E_TOT];            // CSR: src per (dst-sorted) edge
__device__ __align__(16) float d_h1[N_NODES * HID];
__device__ __align__(16) float d_as1[N_NODES * HEADS1];
__device__ __align__(16) float d_ad1[N_NODES * HEADS1];
__device__ __align__(16) float d_hmid[N_NODES * HID];   // elu(gat1 + b1)
__device__ __align__(16) float d_h2[N_NODES * OUT_CH];
__device__ __align__(16) float d_as2[N_NODES];
__device__ __align__(16) float d_ad2[N_NODES];

// Decode edge endpoint i (0..E_REAL-1); which=0 -> src row, which=1 -> dst row.
__device__ __forceinline__ int edge_at(const void* ei, int which, int i) {
    if (d_is64) {
        const long long* p = (const long long*)ei;
        return (int)p[(size_t)which * E_REAL + i];
    } else {
        const int* p = (const int*)ei;
        return p[(size_t)which * E_REAL + i];
    }
}

// ---------------- dtype probe ----------------
// If data is int64, every high 32-bit word is 0 (values < 100000).
// If data is int32, words at odd positions are node ids, ~0 chance all 256 are 0.
__global__ void k_detect(const int* __restrict__ ei32) {
    __shared__ int nz;
    if (threadIdx.x == 0) nz = 0;
    __syncthreads();
    if (ei32[2 * threadIdx.x + 1] != 0) atomicOr(&nz, 1);
    __syncthreads();
    if (threadIdx.x == 0) d_is64 = (nz == 0) ? 1 : 0;
}

// ---------------- CSR build ----------------
__global__ void k_init() {
    int i = blockIdx.x * blockDim.x + threadIdx.x;
    if (i < CNT_PAD) d_cnt[i] = (i < N_NODES) ? 1 : 0;   // 1 = self loop
}

__global__ void k_hist(const void* __restrict__ ei) {
    int i = blockIdx.x * blockDim.x + threadIdx.x;
    if (i < E_REAL) {
        int d = edge_at(ei, 1, i);
        if ((unsigned)d < N_NODES) atomicAdd(&d_cnt[d], 1);
    }
}

__global__ void k_scan_part() {            // 196 blocks x 256 thr
    __shared__ int s[256];
    int b = blockIdx.x, t = threadIdx.x;
    int i0 = b * 512 + t;
    int v = d_cnt[i0] + d_cnt[i0 + 256];
    s[t] = v; __syncthreads();
    for (int off = 128; off > 0; off >>= 1) {
        if (t < off) s[t] += s[t + off];
        __syncthreads();
    }
    if (t == 0) d_part[b] = s[0];
}

__global__ void k_scan_top() {             // 1 block x 256 thr
    __shared__ int s[256];
    int t = threadIdx.x;
    int v = (t < 196) ? d_part[t] : 0;
    s[t] = v; __syncthreads();
    for (int off = 1; off < 256; off <<= 1) {
        int x = (t >= off) ? s[t - off] : 0;
        __syncthreads();
        s[t] += x;
        __syncthreads();
    }
    if (t < 196) d_part[t] = s[t] - v;     // exclusive
}

__global__ void k_scan_chunk() {           // 196 blocks x 512 thr
    __shared__ int s[512];
    int b = blockIdx.x, t = threadIdx.x;
    int i = b * 512 + t;
    int v = d_cnt[i];
    s[t] = v; __syncthreads();
    for (int off = 1; off < 512; off <<= 1) {
        int x = (t >= off) ? s[t - off] : 0;
        __syncthreads();
        s[t] += x;
        __syncthreads();
    }
    if (i <= N_NODES) d_rowptr[i] = d_part[b] + s[t] - v;
}

__global__ void k_selfloop() {
    int i = blockIdx.x * blockDim.x + threadIdx.x;
    if (i < N_NODES) {
        int p = d_rowptr[i];
        d_col[p] = i;          // self loop first
        d_cnt[i] = p + 1;      // cursor
    }
}

__global__ void k_scatter(const void* __restrict__ ei) {
    int i = blockIdx.x * blockDim.x + threadIdx.x;
    if (i < E_REAL) {
        int s = edge_at(ei, 0, i);
        int d = edge_at(ei, 1, i);
        if ((unsigned)d < N_NODES && (unsigned)s < N_NODES) {
            int p = atomicAdd(&d_cnt[d], 1);
            d_col[p] = s;
        }
    }
}

// ---------------- GEMM1: h1 = x @ W1  (100000x256 @ 256x64), fp32 tiled ----------------
__global__ void __launch_bounds__(256) k_gemm1(const float* __restrict__ x,
                                               const float* __restrict__ W) {
    __shared__ float xs[32][129];   // [kk][row], padded
    __shared__ float ws[32][64];    // [kk][col]
    int t = threadIdx.x;
    int tx = t & 15, ty = t >> 4;
    int row0 = blockIdx.x * 128;
    float acc[8][4] = {};

    for (int k0 = 0; k0 < IN_CH; k0 += 32) {
        #pragma unroll
        for (int j = 0; j < 4; j++) {            // x tile: 1024 float4
            int f4 = t + 256 * j;
            int r = f4 >> 3, k4 = f4 & 7;
            int grow = row0 + r;
            float4 v = (grow < N_NODES)
                ? *(const float4*)(x + (size_t)grow * IN_CH + k0 + k4 * 4)
                : make_float4(0.f, 0.f, 0.f, 0.f);
            xs[k4 * 4 + 0][r] = v.x; xs[k4 * 4 + 1][r] = v.y;
            xs[k4 * 4 + 2][r] = v.z; xs[k4 * 4 + 3][r] = v.w;
        }
        #pragma unroll
        for (int j = 0; j < 2; j++) {            // W tile: 512 float4
            int f4 = t + 256 * j;
            int kk = f4 >> 4, c4 = f4 & 15;
            *(float4*)&ws[kk][c4 * 4] = *(const float4*)(W + (k0 + kk) * HID + c4 * 4);
        }
        __syncthreads();
        #pragma unroll
        for (int kk = 0; kk < 32; kk++) {
            float4 wv = *(float4*)&ws[kk][tx * 4];
            #pragma unroll
            for (int i = 0; i < 8; i++) {
                float xv = xs[kk][ty + 16 * i];
                acc[i][0] = fmaf(xv, wv.x, acc[i][0]);
                acc[i][1] = fmaf(xv, wv.y, acc[i][1]);
                acc[i][2] = fmaf(xv, wv.z, acc[i][2]);
                acc[i][3] = fmaf(xv, wv.w, acc[i][3]);
            }
        }
        __syncthreads();
    }
    #pragma unroll
    for (int i = 0; i < 8; i++) {
        int grow = row0 + ty + 16 * i;
        if (grow < N_NODES)
            *(float4*)(d_h1 + (size_t)grow * HID + tx * 4) =
                make_float4(acc[i][0], acc[i][1], acc[i][2], acc[i][3]);
    }
}

// ---------------- alpha for layer 1: per (node, head) ----------------
__global__ void k_alpha1(const float* __restrict__ a_src, const float* __restrict__ a_dst) {
    int i = blockIdx.x * blockDim.x + threadIdx.x;   // i = n*8 + h
    if (i >= N_NODES * HEADS1) return;
    int h = i & 7;
    const float* hp = d_h1 + (size_t)i * 8;
    float4 v0 = *(const float4*)hp;
    float4 v1 = *(const float4*)(hp + 4);
    float as = v0.x * a_src[h * 8 + 0] + v0.y * a_src[h * 8 + 1]
             + v0.z * a_src[h * 8 + 2] + v0.w * a_src[h * 8 + 3]
             + v1.x * a_src[h * 8 + 4] + v1.y * a_src[h * 8 + 5]
             + v1.z * a_src[h * 8 + 6] + v1.w * a_src[h * 8 + 7];
    float ad = v0.x * a_dst[h * 8 + 0] + v0.y * a_dst[h * 8 + 1]
             + v0.z * a_dst[h * 8 + 2] + v0.w * a_dst[h * 8 + 3]
             + v1.x * a_dst[h * 8 + 4] + v1.y * a_dst[h * 8 + 5]
             + v1.z * a_dst[h * 8 + 6] + v1.w * a_dst[h * 8 + 7];
    d_as1[i] = as;
    d_ad1[i] = ad;
}

// ---------------- GAT pull layer 1: warp per dst node, lane owns 2 channels ----------------
// Each lane iterates ALL edges of the node -> each lane already has the FULL wsum
// for its head. No cross-lane reduction of wsum (that was the round-2 bug).
__global__ void __launch_bounds__(128) k_pull1(const float* __restrict__ b1) {
    int n = blockIdx.x * 4 + (threadIdx.x >> 5);
    if (n >= N_NODES) return;
    int lane = threadIdx.x & 31;
    int c2 = lane * 2;
    int hd = lane >> 2;              // 4 lanes per head
    float adv = d_ad1[n * HEADS1 + hd];
    int e0 = d_rowptr[n], e1 = d_rowptr[n + 1];
    float ax = 0.f, ay = 0.f, wsum = 0.f;
    for (int e = e0; e < e1; e++) {
        int s = __ldg(&d_col[e]);
        float al = __ldg(&d_as1[s * HEADS1 + hd]) + adv;
        al = al > 0.f ? al : 0.2f * al;        // leaky_relu
        float w = __expf(al);                  // logits bounded; no max-shift needed
        float2 hv = *(const float2*)(d_h1 + (size_t)s * HID + c2);
        ax = fmaf(w, hv.x, ax);
        ay = fmaf(w, hv.y, ay);
        wsum += w;
    }
    float inv = 1.0f / (wsum + 1e-16f);
    float vx = ax * inv + b1[c2];
    float vy = ay * inv + b1[c2 + 1];
    vx = vx > 0.f ? vx : expm1f(vx);           // elu
    vy = vy > 0.f ? vy : expm1f(vy);
    *(float2*)(d_hmid + (size_t)n * HID + c2) = make_float2(vx, vy);
}

// ---------------- layer 2 node stage: h2 = hmid @ W2, alpha2 ----------------
__global__ void k_l2node(const float* __restrict__ W2,
                         const float* __restrict__ a_src2,
                         const float* __restrict__ a_dst2) {
    __shared__ float sW[HID * OUT_CH];
    __shared__ float sa[OUT_CH], sd[OUT_CH];
    int t = threadIdx.x;
    if (t < HID * OUT_CH) sW[t] = W2[t];
    if (t < OUT_CH) { sa[t] = a_src2[t]; sd[t] = a_dst2[t]; }
    __syncthreads();
    int n = blockIdx.x * blockDim.x + t;
    if (n >= N_NODES) return;
    const float* hp = d_hmid + (size_t)n * HID;
    float o0 = 0.f, o1 = 0.f, o2 = 0.f;
    #pragma unroll
    for (int k = 0; k < HID; k += 4) {
        float4 v = *(const float4*)(hp + k);
        o0 += v.x * sW[k * 3 + 0] + v.y * sW[(k + 1) * 3 + 0] + v.z * sW[(k + 2) * 3 + 0] + v.w * sW[(k + 3) * 3 + 0];
        o1 += v.x * sW[k * 3 + 1] + v.y * sW[(k + 1) * 3 + 1] + v.z * sW[(k + 2) * 3 + 1] + v.w * sW[(k + 3) * 3 + 1];
        o2 += v.x * sW[k * 3 + 2] + v.y * sW[(k + 1) * 3 + 2] + v.z * sW[(k + 2) * 3 + 2] + v.w * sW[(k + 3) * 3 + 2];
    }
    d_h2[n * 3 + 0] = o0; d_h2[n * 3 + 1] = o1; d_h2[n * 3 + 2] = o2;
    d_as2[n] = o0 * sa[0] + o1 * sa[1] + o2 * sa[2];
    d_ad2[n] = o0 * sd[0] + o1 * sd[1] + o2 * sd[2];
}

// ---------------- GAT pull layer 2: warp per dst node, lane per edge ----------------
__global__ void __launch_bounds__(128) k_pull2(float* __restrict__ out,
                                               const float* __restrict__ b2) {
    int n = blockIdx.x * 4 + (threadIdx.x >> 5);
    if (n >= N_NODES) return;
    int lane = threadIdx.x & 31;
    int e0 = d_rowptr[n], e1 = d_rowptr[n + 1];
    float adv = d_ad2[n];
    float a0 = 0.f, a1 = 0.f, a2 = 0.f, wsum = 0.f;
    for (int e = e0 + lane; e < e1; e += 32) {
        int s = __ldg(&d_col[e]);
        float al = __ldg(&d_as2[s]) + adv;
        al = al > 0.f ? al : 0.2f * al;
        float w = __expf(al);
        a0 = fmaf(w, __ldg(&d_h2[s * 3 + 0]), a0);
        a1 = fmaf(w, __ldg(&d_h2[s * 3 + 1]), a1);
        a2 = fmaf(w, __ldg(&d_h2[s * 3 + 2]), a2);
        wsum += w;
    }
    #pragma unroll
    for (int o = 16; o > 0; o >>= 1) {
        a0 += __shfl_xor_sync(0xffffffffu, a0, o);
        a1 += __shfl_xor_sync(0xffffffffu, a1, o);
        a2 += __shfl_xor_sync(0xffffffffu, a2, o);
        wsum += __shfl_xor_sync(0xffffffffu, wsum, o);
    }
    if (lane < 3) {
        float inv = 1.0f / (wsum + 1e-16f);
        float v = (lane == 0) ? a0 : ((lane == 1) ? a1 : a2);
        out[n * 3 + lane] = v * inv + b2[lane];
    }
}

// ---------------- launch ----------------
extern "C" void kernel_launch(void* const* d_in, const int* in_sizes, int n_in,
                              void* d_out, int out_size) {
    const float* x      = (const float*)d_in[0];
    const void*  ei     = d_in[1];
    const float* W1     = (const float*)d_in[2];
    const float* a_src1 = (const float*)d_in[3];
    const float* a_dst1 = (const float*)d_in[4];
    const float* b1     = (const float*)d_in[5];
    const float* W2     = (const float*)d_in[6];
    const float* a_src2 = (const float*)d_in[7];
    const float* a_dst2 = (const float*)d_in[8];
    const float* b2     = (const float*)d_in[9];
    float* out = (float*)d_out;

    // dtype probe + CSR build (shared by both layers)
    k_detect<<<1, 256>>>((const int*)ei);
    k_init<<<(CNT_PAD + 255) / 256, 256>>>();
    k_hist<<<(E_REAL + 255) / 256, 256>>>(ei);
    k_scan_part<<<196, 256>>>();
    k_scan_top<<<1, 256>>>();
    k_scan_chunk<<<196, 512>>>();
    k_selfloop<<<(N_NODES + 255) / 256, 256>>>();
    k_scatter<<<(E_REAL + 255) / 256, 256>>>(ei);

    // Layer 1
    k_gemm1<<<(N_NODES + 127) / 128, 256>>>(x, W1);
    k_alpha1<<<(N_NODES * HEADS1 + 255) / 256, 256>>>(a_src1, a_dst1);
    k_pull1<<<(N_NODES + 3) / 4, 128>>>(b1);

    // Layer 2
    k_l2node<<<(N_NODES + 255) / 256, 256>>>(W2, a_src2, a_dst2);
    k_pull2<<<(N_NODES + 3) / 4, 128>>>(out, b2);
}